// round 16
// baseline (speedup 1.0000x reference)
#include <cuda_runtime.h>
#include <math.h>

#define Bsz 4096
#define Tsz 64
#define Fsz 37
#define TB 8          // batch elements per CTA
#define NP 24         // TB * 3 timesteps
#define NT 128        // LSTM kernel threads (one per hidden unit)
#define NTF 256       // front-end kernel threads
#define FDIM 150      // lin width
#define LINP 152      // padded lin stride (608B rows, 16B aligned)
#define FP4 38        // ceil(FDIM/4) quad-f groups (padded with zeros)
#define KP4 32        // H/4 quad-k groups
#define GATES 512
#define H 128
#define RGRID 76      // repack CTAs folded into front-end launch

typedef unsigned long long ull;

// ---- global scratch: quad-f packed LSTM weights, gate-interleaved ----
// g_wk4[(fq*4 + c)*H + j] : one base pointer, gates at +c*H*16B immediates
__device__ ulonglong2 g_wk4[FP4 * 4 * H];
__device__ ulonglong2 g_wr4[KP4 * 4 * H];
__device__ float g_lin[(Bsz / TB) * NP * LINP];  // 7.5 MB lin scratch

// shared memory layout (floats) — shared by both kernels
#define OFF_FEAT 0        // 24*37 = 888 (aliased by head buffers in LSTM kernel)
#define OFF_T1M1 888      // 24*16 = 384
#define OFF_S1   1272     // 24*32 = 768
#define OFF_LIN  2040     // 3*8*152 = 3648 (byte 8160, 16B aligned)
#define OFF_H    5688     // 8*128 = 1024   (byte 22752, 16B aligned)
#define SMEM_FLOATS 6712  // 26848 bytes

struct Params {
    const float *feature;
    const float *w_m1, *b_m1, *w_m2, *b_m2;
    const float *w_t1, *b_t1, *w_t2, *b_t2;
    const float *w_s1, *b_s1, *w_s2, *b_s2;
    const float *w_lk, *w_lr, *b_l;
    const float *w_p1, *b_p1, *w_p2, *b_p2, *w_p3, *b_p3, *w_p4, *b_p4, *w_p5, *b_p5;
    float *out;
};

__device__ __forceinline__ float lrelu(float x) { return x >= 0.f ? x : 0.2f * x; }
__device__ __forceinline__ float sigm(float x) { return 1.f / (1.f + __expf(-x)); }

__device__ __forceinline__ ull pack2(float lo, float hi) {
    ull v;
    asm("mov.b64 %0, {%1, %2};" : "=l"(v) : "f"(lo), "f"(hi));
    return v;
}
__device__ __forceinline__ void unpack2(float &lo, float &hi, ull v) {
    asm("mov.b64 {%0, %1}, %2;" : "=f"(lo), "=f"(hi) : "l"(v));
}
__device__ __forceinline__ void ffma2(ull &acc, ull a, ull b) {
    asm("fma.rn.f32x2 %0, %1, %2, %0;" : "+l"(acc) : "l"(a), "l"(b));
}

// lin batch-major: [t][b][f], f contiguous, stride LINP. row r = t*TB+b
#define LIDX(t, f, b) (((t) * TB + (b)) * LINP + (f))

// ============================================================================
// Front-end kernel: CTAs [0, RGRID) repack LSTM weights; CTAs [RGRID, ...)
// run passes 1-4 at high occupancy and write lin to g_lin.
// ============================================================================
__global__ void __launch_bounds__(NTF) frontend_kernel(Params P) {
    const int tid = threadIdx.x;

    if (blockIdx.x < RGRID) {
        // ---- repack w_lk/w_lr into gate-interleaved quad-f streams ----
        int i = blockIdx.x * NTF + tid;
        if (i < FP4 * 4 * H) {
            int fq = i / (4 * H), r = i % (4 * H);
            int c = r / H, j = r % H;
            float w[4];
            #pragma unroll
            for (int q = 0; q < 4; ++q) {
                int f = 4 * fq + q;
                w[q] = (f < FDIM) ? P.w_lk[f * GATES + c * H + j] : 0.f;
            }
            g_wk4[i] = make_ulonglong2(pack2(w[0], w[1]), pack2(w[2], w[3]));
        }
        if (i < KP4 * 4 * H) {
            int kq = i / (4 * H), r = i % (4 * H);
            int c = r / H, j = r % H;
            float w[4];
            #pragma unroll
            for (int q = 0; q < 4; ++q)
                w[q] = P.w_lr[(4 * kq + q) * GATES + c * H + j];
            g_wr4[i] = make_ulonglong2(pack2(w[0], w[1]), pack2(w[2], w[3]));
        }
        return;
    }

    __shared__ __align__(16) float sm[OFF_H];   // feat, t1m1, S1, linB
    const int grp = blockIdx.x - RGRID;
    const int bg0 = grp * TB;

    float *feat = sm + OFF_FEAT;
    float *t1m1 = sm + OFF_T1M1;
    float *S1   = sm + OFF_S1;
    float *linB = sm + OFF_LIN;

    // ---- load feature rows t=0..2 for 8 batch elems; zero lin pad cols ----
    for (int i = tid; i < NP * Fsz; i += NTF) {
        int p = i / Fsz, f = i % Fsz;
        int b = p / 3, t = p % 3;
        feat[p * Fsz + f] =
            P.feature[(size_t)(bg0 + b) * Tsz * Fsz + (size_t)t * Fsz + f];
    }
    if (tid < NP) {
        linB[tid * LINP + 150] = 0.f;
        linB[tid * LINP + 151] = 0.f;
    }
    __syncthreads();

    // ---- pass1: M1 (q<8) and T1 (q>=8), per (b,t) pair p ----
    for (int i = tid; i < NP * 16; i += NTF) {
        int p = i >> 4, q = i & 15;
        const float *fr = feat + p * Fsz;
        float acc;
        if (q < 8) {
            acc = P.b_m1[q];
            #pragma unroll
            for (int f = 0; f < 3; ++f) acc += fr[33 + f] * P.w_m1[f * 8 + q];
            acc = lrelu(acc);
        } else {
            int j = q - 8;
            acc = P.b_t1[j];
            #pragma unroll
            for (int f = 0; f < Fsz; ++f) acc += fr[f] * P.w_t1[f * 8 + j];
            acc = lrelu(acc);
            acc = fabsf(acc);
        }
        t1m1[i] = acc;
    }
    __syncthreads();

    // ---- pass2: M -> lin[0:16], Tsk -> lin[16:32], Psk -> lin[32:48] ----
    for (int i = tid; i < NP * 32; i += NTF) {
        int p = i >> 5, q = i & 31;
        int b = p / 3, t = p % 3;
        if (q < 16) {
            float acc = P.b_m2[q];
            #pragma unroll
            for (int k = 0; k < 8; ++k) acc += t1m1[p * 16 + k] * P.w_m2[k * 16 + q];
            linB[LIDX(t, q, b)] = lrelu(acc);
        } else {
            int j = q - 16;
            float acc = P.b_t2[j];
            #pragma unroll
            for (int k = 0; k < 8; ++k) acc += t1m1[p * 16 + 8 + k] * P.w_t2[k * 16 + j];
            float v = (acc >= 0.f) ? acc : -0.2f * acc;  // abs(lrelu)
            linB[LIDX(t, 16 + j, b)] = v;
            linB[LIDX(t, 32 + j, b)] = log1pf(v);
        }
    }
    // Pa -> lin[48], feature copy -> lin[113:150]
    for (int i = tid; i < NP * 38; i += NTF) {
        int p = i / 38, q = i % 38;
        int b = p / 3, t = p % 3;
        if (q == 0) linB[LIDX(t, 48, b)] = log1pf(feat[p * Fsz + 31]);
        else        linB[LIDX(t, 113 + (q - 1), b)] = feat[p * Fsz + (q - 1)];
    }
    __syncthreads();

    // ---- pass3: S1 = lrelu(s_in @ w_s1 + b_s1) ----
    for (int i = tid; i < NP * 32; i += NTF) {
        int p = i >> 5, j = i & 31;
        int b = p / 3, t = p % 3;
        float acc = P.b_s1[j];
        for (int f = 0; f < 49; ++f) acc += linB[LIDX(t, f, b)] * P.w_s1[f * 32 + j];
        const float *fr = feat + p * Fsz;
        #pragma unroll
        for (int e = 0; e < 6; ++e) acc += fr[27 + e] * P.w_s1[(49 + e) * 32 + j];
        #pragma unroll
        for (int e = 0; e < 3; ++e) acc += fr[33 + e] * P.w_s1[(55 + e) * 32 + j];
        S1[p * 32 + j] = lrelu(acc);
    }
    __syncthreads();

    // ---- pass4: S -> lin[49:113] ----
    for (int i = tid; i < NP * 64; i += NTF) {
        int p = i >> 6, j = i & 63;
        int b = p / 3, t = p % 3;
        float acc = P.b_s2[j];
        #pragma unroll
        for (int k = 0; k < 32; ++k) acc += S1[p * 32 + k] * P.w_s2[k * 64 + j];
        linB[LIDX(t, 49 + j, b)] = lrelu(acc);
    }
    __syncthreads();

    // ---- copy lin to global scratch (coalesced float4) ----
    float *dst = g_lin + (size_t)grp * (NP * LINP);
    for (int i = tid; i < NP * LINP / 4; i += NTF)
        ((float4 *)dst)[i] = ((const float4 *)linB)[i];
}

// ============================================================================
// LSTM + head kernel. R8 dataflow; gate-interleaved weights (1 base pointer
// per matrix, immediate gate offsets) + float biases to kill register spill
// within the 128-reg / 4-CTA budget.
// ============================================================================
__global__ void __launch_bounds__(NT, 4) lstm_fused_kernel(Params P) {
    __shared__ __align__(16) float sm[SMEM_FLOATS];
    const int tid = threadIdx.x;
    const int bg0 = blockIdx.x * TB;

    float *linB = sm + OFF_LIN;
    float *hB   = sm + OFF_H;     // [b][k], rows 512B

    // ---- load lin slice from global scratch ----
    {
        const float4 *src =
            (const float4 *)(g_lin + (size_t)blockIdx.x * (NP * LINP));
        for (int i = tid; i < NP * LINP / 4; i += NT)
            ((float4 *)linB)[i] = src[i];
    }
    __syncthreads();

    // ---- LSTM: 3 timesteps ----
    {
        const int j = tid;
        const float bi0 = P.b_l[j], bi1 = P.b_l[j + H];
        const float bi2 = P.b_l[j + 2 * H], bi3 = P.b_l[j + 3 * H];
        float cres[TB];
        #pragma unroll
        for (int b = 0; b < TB; ++b) cres[b] = 0.f;

        for (int t = 0; t < 3; ++t) {
            ull acc0[TB], acc1[TB], acc2[TB], acc3[TB];
            #pragma unroll
            for (int b = 0; b < TB; ++b) {
                acc0[b] = pack2(bi0, 0.f);
                acc1[b] = pack2(bi1, 0.f);
                acc2[b] = pack2(bi2, 0.f);
                acc3[b] = pack2(bi3, 0.f);
            }

            // input GEMM: z += lin_t @ w_lk   (38 quad-f groups)
            {
                const ulonglong2 *wp = g_wk4 + j;       // gates at +H imm
                const float *lp = linB + t * TB * LINP; // batches at +LINP imm
                #pragma unroll 2
                for (int fq = 0; fq < FP4; ++fq) {
                    ulonglong2 w0 = wp[0 * H];
                    ulonglong2 w1 = wp[1 * H];
                    ulonglong2 w2 = wp[2 * H];
                    ulonglong2 w3 = wp[3 * H];
                    #pragma unroll
                    for (int b = 0; b < TB; ++b) {
                        ulonglong2 a = *(const ulonglong2 *)(lp + b * LINP);
                        ffma2(acc0[b], a.x, w0.x);
                        ffma2(acc1[b], a.x, w1.x);
                        ffma2(acc2[b], a.x, w2.x);
                        ffma2(acc3[b], a.x, w3.x);
                        ffma2(acc0[b], a.y, w0.y);
                        ffma2(acc1[b], a.y, w1.y);
                        ffma2(acc2[b], a.y, w2.y);
                        ffma2(acc3[b], a.y, w3.y);
                    }
                    wp += 4 * H;
                    lp += 4;
                }
            }
            // recurrent GEMM: z += h @ w_lr   (32 quad-k groups; h==0 at t=0)
            if (t > 0) {
                const ulonglong2 *wp = g_wr4 + j;
                const float *hp = hB;
                #pragma unroll 2
                for (int kq = 0; kq < KP4; ++kq) {
                    ulonglong2 w0 = wp[0 * H];
                    ulonglong2 w1 = wp[1 * H];
                    ulonglong2 w2 = wp[2 * H];
                    ulonglong2 w3 = wp[3 * H];
                    #pragma unroll
                    for (int b = 0; b < TB; ++b) {
                        ulonglong2 a = *(const ulonglong2 *)(hp + b * H);
                        ffma2(acc0[b], a.x, w0.x);
                        ffma2(acc1[b], a.x, w1.x);
                        ffma2(acc2[b], a.x, w2.x);
                        ffma2(acc3[b], a.x, w3.x);
                        ffma2(acc0[b], a.y, w0.y);
                        ffma2(acc1[b], a.y, w1.y);
                        ffma2(acc2[b], a.y, w2.y);
                        ffma2(acc3[b], a.y, w3.y);
                    }
                    wp += 4 * H;
                    hp += 4;
                }
            }

            // all reads of hB (this t) must finish before overwrite
            __syncthreads();

            // lane-add + gates + state update, fully in registers
            #pragma unroll
            for (int b = 0; b < TB; ++b) {
                float zi_l, zi_h, zf_l, zf_h, zg_l, zg_h, zo_l, zo_h;
                unpack2(zi_l, zi_h, acc0[b]);
                unpack2(zf_l, zf_h, acc1[b]);
                unpack2(zg_l, zg_h, acc2[b]);
                unpack2(zo_l, zo_h, acc3[b]);
                float zi = zi_l + zi_h, zf = zf_l + zf_h;
                float zg = zg_l + zg_h, zo = zo_l + zo_h;
                float cv = sigm(zf) * cres[b] + sigm(zi) * lrelu(zg);
                cres[b] = cv;
                hB[b * H + j] = sigm(zo) * lrelu(cv);
            }
            __syncthreads();
        }
    }

    // ---- head at t=2 (buffers alias dead smem region [0, 2040)) ----
    float *d1 = sm;        // 8*64 = 512
    float *d2 = sm + 512;  // 8*32
    float *d3 = sm + 768;  // 8*16
    float *d4 = sm + 896;  // 8*8
    float *d5 = sm + 960;  // 8*3

    for (int i = tid; i < TB * 64; i += NT) {
        int b = i >> 6, j = i & 63;
        float acc = P.b_p1[j];
        for (int k = 0; k < H; ++k) acc += hB[b * H + k] * P.w_p1[k * 64 + j];
        d1[i] = lrelu(acc);
    }
    __syncthreads();
    for (int i = tid; i < TB * 32; i += NT) {
        int b = i >> 5, j = i & 31;
        float acc = P.b_p2[j];
        #pragma unroll
        for (int k = 0; k < 64; ++k) acc += d1[b * 64 + k] * P.w_p2[k * 32 + j];
        d2[i] = lrelu(acc);
    }
    __syncthreads();
    for (int i = tid; i < TB * 16; i += NT) {
        int b = i >> 4, j = i & 15;
        float acc = P.b_p3[j];
        #pragma unroll
        for (int k = 0; k < 32; ++k) acc += d2[b * 32 + k] * P.w_p3[k * 16 + j];
        d3[i] = lrelu(acc);
    }
    __syncthreads();
    for (int i = tid; i < TB * 8; i += NT) {
        int b = i >> 3, j = i & 7;
        float acc = P.b_p4[j];
        #pragma unroll
        for (int k = 0; k < 16; ++k) acc += d3[b * 16 + k] * P.w_p4[k * 8 + j];
        d4[i] = lrelu(acc);
    }
    __syncthreads();
    for (int i = tid; i < TB * 3; i += NT) {
        int b = i / 3, j = i % 3;
        float acc = P.b_p5[j];
        #pragma unroll
        for (int k = 0; k < 8; ++k) acc += d4[b * 8 + k] * P.w_p5[k * 3 + j];
        d5[i] = lrelu(acc);
    }
    __syncthreads();

    // ---- softmax + write both outputs ----
    if (tid < TB) {
        int b = tid;
        float l0 = d5[b * 3 + 0], l1 = d5[b * 3 + 1], l2 = d5[b * 3 + 2];
        float m = fmaxf(l0, fmaxf(l1, l2));
        float e0 = __expf(l0 - m), e1 = __expf(l1 - m), e2 = __expf(l2 - m);
        float inv = 1.f / (e0 + e1 + e2);
        float o0 = e0 * inv, o1 = e1 * inv, o2 = e2 * inv;
        size_t gb = (size_t)(bg0 + b);
        float *outp = P.out + gb * 3;
        outp[0] = o0; outp[1] = o1; outp[2] = o2;
        float *xp = P.out + (size_t)Bsz * 3 + gb * 13;
        const float *fsrc = P.feature + gb * Tsz * Fsz + 2 * Fsz + 27;
        #pragma unroll
        for (int q = 0; q < 10; ++q) xp[q] = fsrc[q];
        xp[10] = o0; xp[11] = o1; xp[12] = o2;
    }
}

extern "C" void kernel_launch(void *const *d_in, const int *in_sizes, int n_in,
                              void *d_out, int out_size) {
    Params P;
    P.feature = (const float *)d_in[0];
    P.w_m1 = (const float *)d_in[1];  P.b_m1 = (const float *)d_in[2];
    P.w_m2 = (const float *)d_in[3];  P.b_m2 = (const float *)d_in[4];
    P.w_t1 = (const float *)d_in[5];  P.b_t1 = (const float *)d_in[6];
    P.w_t2 = (const float *)d_in[7];  P.b_t2 = (const float *)d_in[8];
    P.w_s1 = (const float *)d_in[9];  P.b_s1 = (const float *)d_in[10];
    P.w_s2 = (const float *)d_in[11]; P.b_s2 = (const float *)d_in[12];
    P.w_lk = (const float *)d_in[13];
    P.w_lr = (const float *)d_in[14];
    P.b_l  = (const float *)d_in[15];
    P.w_p1 = (const float *)d_in[16]; P.b_p1 = (const float *)d_in[17];
    P.w_p2 = (const float *)d_in[18]; P.b_p2 = (const float *)d_in[19];
    P.w_p3 = (const float *)d_in[20]; P.b_p3 = (const float *)d_in[21];
    P.w_p4 = (const float *)d_in[22]; P.b_p4 = (const float *)d_in[23];
    P.w_p5 = (const float *)d_in[24]; P.b_p5 = (const float *)d_in[25];
    P.out = (float *)d_out;

    frontend_kernel<<<RGRID + Bsz / TB, NTF>>>(P);
    lstm_fused_kernel<<<Bsz / TB, NT>>>(P);
}

// round 17
// speedup vs baseline: 1.0910x; 1.0910x over previous
#include <cuda_runtime.h>
#include <math.h>

#define Bsz 4096
#define Tsz 64
#define Fsz 37
#define TB 10         // batch elements per LSTM CTA (last CTA ragged)
#define NP 30         // TB * 3 timesteps (LSTM kernel smem rows)
#define TBF 8         // batch elements per front-end CTA
#define NPF 24        // TBF * 3
#define NT 128        // LSTM kernel threads (one per hidden unit)
#define NTF 256       // front-end kernel threads
#define FDIM 150      // lin width
#define LINP 152      // padded lin stride (608B rows, 16B aligned)
#define FP4 38        // ceil(FDIM/4) quad-f groups (padded with zeros)
#define KP4 32        // H/4 quad-k groups
#define GATES 512
#define H 128
#define RGRID 76      // repack CTAs folded into front-end launch
#define GRID_L ((Bsz + TB - 1) / TB)   // 410 LSTM CTAs (<= 444 = 148*3)

typedef unsigned long long ull;

// ---- global scratch ----
// gate-interleaved quad-f LSTM weights: g_wk4[(fq*4 + c)*H + j]
__device__ ulonglong2 g_wk4[FP4 * 4 * H];
__device__ ulonglong2 g_wr4[KP4 * 4 * H];
// lin, batch-major: row (batch*3 + t), stride LINP  (7.5 MB)
__device__ float g_lin[Bsz * 3 * LINP];

// ---- LSTM kernel smem layout (floats) ----
#define OFF_LIN  2040     // 3*10*152 = 4560 (byte 8160; [0,2040) = head scratch)
#define OFF_H    6600     // 10*128 = 1280  (byte 26400, 16B aligned)
#define SMEM_FLOATS 7880  // 31520 bytes

// ---- front-end kernel smem layout (floats) ----
#define F_FEAT 0          // 24*37 = 888
#define F_T1M1 888        // 24*16 = 384
#define F_S1   1272       // 24*32 = 768
#define F_LIN  2040       // 3*8*152 = 3648
#define F_SMEM 5688

struct Params {
    const float *feature;
    const float *w_m1, *b_m1, *w_m2, *b_m2;
    const float *w_t1, *b_t1, *w_t2, *b_t2;
    const float *w_s1, *b_s1, *w_s2, *b_s2;
    const float *w_lk, *w_lr, *b_l;
    const float *w_p1, *b_p1, *w_p2, *b_p2, *w_p3, *b_p3, *w_p4, *b_p4, *w_p5, *b_p5;
    float *out;
};

__device__ __forceinline__ float lrelu(float x) { return x >= 0.f ? x : 0.2f * x; }
__device__ __forceinline__ float sigm(float x) { return 1.f / (1.f + __expf(-x)); }

__device__ __forceinline__ ull pack2(float lo, float hi) {
    ull v;
    asm("mov.b64 %0, {%1, %2};" : "=l"(v) : "f"(lo), "f"(hi));
    return v;
}
__device__ __forceinline__ void unpack2(float &lo, float &hi, ull v) {
    asm("mov.b64 {%0, %1}, %2;" : "=f"(lo), "=f"(hi) : "l"(v));
}
__device__ __forceinline__ void ffma2(ull &acc, ull a, ull b) {
    asm("fma.rn.f32x2 %0, %1, %2, %0;" : "+l"(acc) : "l"(a), "l"(b));
}

#define LIDXF(t, f, b) (((t) * TBF + (b)) * LINP + (f))   // front-end smem
#define LIDX(t, f, b)  (((t) * TB + (b)) * LINP + (f))    // LSTM smem

// ============================================================================
// Front-end kernel: CTAs [0, RGRID) repack LSTM weights; CTAs [RGRID, ...)
// run passes 1-4 at high occupancy and write lin rows to batch-major g_lin.
// ============================================================================
__global__ void __launch_bounds__(NTF) frontend_kernel(Params P) {
    const int tid = threadIdx.x;

    if (blockIdx.x < RGRID) {
        int i = blockIdx.x * NTF + tid;
        if (i < FP4 * 4 * H) {
            int fq = i / (4 * H), r = i % (4 * H);
            int c = r / H, j = r % H;
            float w[4];
            #pragma unroll
            for (int q = 0; q < 4; ++q) {
                int f = 4 * fq + q;
                w[q] = (f < FDIM) ? P.w_lk[f * GATES + c * H + j] : 0.f;
            }
            g_wk4[i] = make_ulonglong2(pack2(w[0], w[1]), pack2(w[2], w[3]));
        }
        if (i < KP4 * 4 * H) {
            int kq = i / (4 * H), r = i % (4 * H);
            int c = r / H, j = r % H;
            float w[4];
            #pragma unroll
            for (int q = 0; q < 4; ++q)
                w[q] = P.w_lr[(4 * kq + q) * GATES + c * H + j];
            g_wr4[i] = make_ulonglong2(pack2(w[0], w[1]), pack2(w[2], w[3]));
        }
        return;
    }

    __shared__ __align__(16) float sm[F_SMEM];
    const int grp = blockIdx.x - RGRID;
    const int bg0 = grp * TBF;

    float *feat = sm + F_FEAT;
    float *t1m1 = sm + F_T1M1;
    float *S1   = sm + F_S1;
    float *linB = sm + F_LIN;

    for (int i = tid; i < NPF * Fsz; i += NTF) {
        int p = i / Fsz, f = i % Fsz;
        int b = p / 3, t = p % 3;
        feat[p * Fsz + f] =
            P.feature[(size_t)(bg0 + b) * Tsz * Fsz + (size_t)t * Fsz + f];
    }
    if (tid < NPF) {
        linB[tid * LINP + 150] = 0.f;
        linB[tid * LINP + 151] = 0.f;
    }
    __syncthreads();

    // pass1
    for (int i = tid; i < NPF * 16; i += NTF) {
        int p = i >> 4, q = i & 15;
        const float *fr = feat + p * Fsz;
        float acc;
        if (q < 8) {
            acc = P.b_m1[q];
            #pragma unroll
            for (int f = 0; f < 3; ++f) acc += fr[33 + f] * P.w_m1[f * 8 + q];
            acc = lrelu(acc);
        } else {
            int j = q - 8;
            acc = P.b_t1[j];
            #pragma unroll
            for (int f = 0; f < Fsz; ++f) acc += fr[f] * P.w_t1[f * 8 + j];
            acc = lrelu(acc);
            acc = fabsf(acc);
        }
        t1m1[i] = acc;
    }
    __syncthreads();

    // pass2
    for (int i = tid; i < NPF * 32; i += NTF) {
        int p = i >> 5, q = i & 31;
        int b = p / 3, t = p % 3;
        if (q < 16) {
            float acc = P.b_m2[q];
            #pragma unroll
            for (int k = 0; k < 8; ++k) acc += t1m1[p * 16 + k] * P.w_m2[k * 16 + q];
            linB[LIDXF(t, q, b)] = lrelu(acc);
        } else {
            int j = q - 16;
            float acc = P.b_t2[j];
            #pragma unroll
            for (int k = 0; k < 8; ++k) acc += t1m1[p * 16 + 8 + k] * P.w_t2[k * 16 + j];
            float v = (acc >= 0.f) ? acc : -0.2f * acc;
            linB[LIDXF(t, 16 + j, b)] = v;
            linB[LIDXF(t, 32 + j, b)] = log1pf(v);
        }
    }
    for (int i = tid; i < NPF * 38; i += NTF) {
        int p = i / 38, q = i % 38;
        int b = p / 3, t = p % 3;
        if (q == 0) linB[LIDXF(t, 48, b)] = log1pf(feat[p * Fsz + 31]);
        else        linB[LIDXF(t, 113 + (q - 1), b)] = feat[p * Fsz + (q - 1)];
    }
    __syncthreads();

    // pass3
    for (int i = tid; i < NPF * 32; i += NTF) {
        int p = i >> 5, j = i & 31;
        int b = p / 3, t = p % 3;
        float acc = P.b_s1[j];
        for (int f = 0; f < 49; ++f) acc += linB[LIDXF(t, f, b)] * P.w_s1[f * 32 + j];
        const float *fr = feat + p * Fsz;
        #pragma unroll
        for (int e = 0; e < 6; ++e) acc += fr[27 + e] * P.w_s1[(49 + e) * 32 + j];
        #pragma unroll
        for (int e = 0; e < 3; ++e) acc += fr[33 + e] * P.w_s1[(55 + e) * 32 + j];
        S1[p * 32 + j] = lrelu(acc);
    }
    __syncthreads();

    // pass4
    for (int i = tid; i < NPF * 64; i += NTF) {
        int p = i >> 6, j = i & 63;
        int b = p / 3, t = p % 3;
        float acc = P.b_s2[j];
        #pragma unroll
        for (int k = 0; k < 32; ++k) acc += S1[p * 32 + k] * P.w_s2[k * 64 + j];
        linB[LIDXF(t, 49 + j, b)] = lrelu(acc);
    }
    __syncthreads();

    // ---- write lin rows to batch-major g_lin (row = (bg0+b)*3 + t) ----
    for (int i = tid; i < NPF * (LINP / 4); i += NTF) {
        int dr = i / (LINP / 4), q = i % (LINP / 4);
        int b = dr / 3, t = dr % 3;
        float4 *dst = (float4 *)(g_lin + ((size_t)(bg0 + b) * 3 + t) * LINP);
        dst[q] = ((const float4 *)(linB + LIDXF(t, 0, b)))[q];
    }
}

// ============================================================================
// LSTM + head kernel: TB=10, 410 CTAs, spill-free at 3 CTAs/SM, single wave.
// ============================================================================
__global__ void __launch_bounds__(NT, 3) lstm_fused_kernel(Params P) {
    __shared__ __align__(16) float sm[SMEM_FLOATS];
    const int tid = threadIdx.x;
    const int bg0 = blockIdx.x * TB;

    float *linB = sm + OFF_LIN;
    float *hB   = sm + OFF_H;     // [b][k], rows 512B

    // ---- load lin rows from g_lin (clamp ragged tail to batch Bsz-1) ----
    for (int i = tid; i < NP * (LINP / 4); i += NT) {
        int r = i / (LINP / 4), q = i % (LINP / 4);
        int t = r / TB, b = r % TB;
        int gb = bg0 + b;
        if (gb > Bsz - 1) gb = Bsz - 1;
        const float4 *src = (const float4 *)(g_lin + ((size_t)gb * 3 + t) * LINP);
        ((float4 *)(linB + r * LINP))[q] = src[q];
    }
    __syncthreads();

    // ---- LSTM: 3 timesteps ----
    {
        const int j = tid;
        const float bi0 = P.b_l[j], bi1 = P.b_l[j + H];
        const float bi2 = P.b_l[j + 2 * H], bi3 = P.b_l[j + 3 * H];
        float cres[TB];
        #pragma unroll
        for (int b = 0; b < TB; ++b) cres[b] = 0.f;

        for (int t = 0; t < 3; ++t) {
            ull acc0[TB], acc1[TB], acc2[TB], acc3[TB];
            #pragma unroll
            for (int b = 0; b < TB; ++b) {
                acc0[b] = pack2(bi0, 0.f);
                acc1[b] = pack2(bi1, 0.f);
                acc2[b] = pack2(bi2, 0.f);
                acc3[b] = pack2(bi3, 0.f);
            }

            // input GEMM: z += lin_t @ w_lk   (38 quad-f groups)
            {
                const ulonglong2 *wp = g_wk4 + j;       // gates at +H imm
                const float *lp = linB + t * TB * LINP; // batches at +LINP imm
                #pragma unroll 2
                for (int fq = 0; fq < FP4; ++fq) {
                    ulonglong2 w0 = wp[0 * H];
                    ulonglong2 w1 = wp[1 * H];
                    ulonglong2 w2 = wp[2 * H];
                    ulonglong2 w3 = wp[3 * H];
                    #pragma unroll
                    for (int b = 0; b < TB; ++b) {
                        ulonglong2 a = *(const ulonglong2 *)(lp + b * LINP);
                        ffma2(acc0[b], a.x, w0.x);
                        ffma2(acc1[b], a.x, w1.x);
                        ffma2(acc2[b], a.x, w2.x);
                        ffma2(acc3[b], a.x, w3.x);
                        ffma2(acc0[b], a.y, w0.y);
                        ffma2(acc1[b], a.y, w1.y);
                        ffma2(acc2[b], a.y, w2.y);
                        ffma2(acc3[b], a.y, w3.y);
                    }
                    wp += 4 * H;
                    lp += 4;
                }
            }
            // recurrent GEMM: z += h @ w_lr   (32 quad-k groups; h==0 at t=0)
            if (t > 0) {
                const ulonglong2 *wp = g_wr4 + j;
                const float *hp = hB;
                #pragma unroll 2
                for (int kq = 0; kq < KP4; ++kq) {
                    ulonglong2 w0 = wp[0 * H];
                    ulonglong2 w1 = wp[1 * H];
                    ulonglong2 w2 = wp[2 * H];
                    ulonglong2 w3 = wp[3 * H];
                    #pragma unroll
                    for (int b = 0; b < TB; ++b) {
                        ulonglong2 a = *(const ulonglong2 *)(hp + b * H);
                        ffma2(acc0[b], a.x, w0.x);
                        ffma2(acc1[b], a.x, w1.x);
                        ffma2(acc2[b], a.x, w2.x);
                        ffma2(acc3[b], a.x, w3.x);
                        ffma2(acc0[b], a.y, w0.y);
                        ffma2(acc1[b], a.y, w1.y);
                        ffma2(acc2[b], a.y, w2.y);
                        ffma2(acc3[b], a.y, w3.y);
                    }
                    wp += 4 * H;
                    hp += 4;
                }
            }

            __syncthreads();   // hB reads done before overwrite

            #pragma unroll
            for (int b = 0; b < TB; ++b) {
                float zi_l, zi_h, zf_l, zf_h, zg_l, zg_h, zo_l, zo_h;
                unpack2(zi_l, zi_h, acc0[b]);
                unpack2(zf_l, zf_h, acc1[b]);
                unpack2(zg_l, zg_h, acc2[b]);
                unpack2(zo_l, zo_h, acc3[b]);
                float zi = zi_l + zi_h, zf = zf_l + zf_h;
                float zg = zg_l + zg_h, zo = zo_l + zo_h;
                float cv = sigm(zf) * cres[b] + sigm(zi) * lrelu(zg);
                cres[b] = cv;
                hB[b * H + j] = sigm(zo) * lrelu(cv);
            }
            __syncthreads();
        }
    }

    // ---- head at t=2 (buffers alias smem region [0, 2040)) ----
    float *d1 = sm;         // 10*64 = 640
    float *d2 = sm + 640;   // 10*32 = 320
    float *d3 = sm + 960;   // 10*16 = 160
    float *d4 = sm + 1120;  // 10*8  = 80
    float *d5 = sm + 1200;  // 10*3  = 30

    for (int i = tid; i < TB * 64; i += NT) {
        int b = i >> 6, j = i & 63;
        float acc = P.b_p1[j];
        for (int k = 0; k < H; ++k) acc += hB[b * H + k] * P.w_p1[k * 64 + j];
        d1[i] = lrelu(acc);
    }
    __syncthreads();
    for (int i = tid; i < TB * 32; i += NT) {
        int b = i >> 5, j = i & 31;
        float acc = P.b_p2[j];
        #pragma unroll
        for (int k = 0; k < 64; ++k) acc += d1[b * 64 + k] * P.w_p2[k * 32 + j];
        d2[i] = lrelu(acc);
    }
    __syncthreads();
    for (int i = tid; i < TB * 16; i += NT) {
        int b = i >> 4, j = i & 15;
        float acc = P.b_p3[j];
        #pragma unroll
        for (int k = 0; k < 32; ++k) acc += d2[b * 32 + k] * P.w_p3[k * 16 + j];
        d3[i] = lrelu(acc);
    }
    __syncthreads();
    for (int i = tid; i < TB * 8; i += NT) {
        int b = i >> 3, j = i & 7;
        float acc = P.b_p4[j];
        #pragma unroll
        for (int k = 0; k < 16; ++k) acc += d3[b * 16 + k] * P.w_p4[k * 8 + j];
        d4[i] = lrelu(acc);
    }
    __syncthreads();
    for (int i = tid; i < TB * 3; i += NT) {
        int b = i / 3, j = i % 3;
        float acc = P.b_p5[j];
        #pragma unroll
        for (int k = 0; k < 8; ++k) acc += d4[b * 8 + k] * P.w_p5[k * 3 + j];
        d5[i] = lrelu(acc);
    }
    __syncthreads();

    // ---- softmax + write both outputs (guard ragged tail) ----
    if (tid < TB && bg0 + tid < Bsz) {
        int b = tid;
        float l0 = d5[b * 3 + 0], l1 = d5[b * 3 + 1], l2 = d5[b * 3 + 2];
        float m = fmaxf(l0, fmaxf(l1, l2));
        float e0 = __expf(l0 - m), e1 = __expf(l1 - m), e2 = __expf(l2 - m);
        float inv = 1.f / (e0 + e1 + e2);
        float o0 = e0 * inv, o1 = e1 * inv, o2 = e2 * inv;
        size_t gb = (size_t)(bg0 + b);
        float *outp = P.out + gb * 3;
        outp[0] = o0; outp[1] = o1; outp[2] = o2;
        float *xp = P.out + (size_t)Bsz * 3 + gb * 13;
        const float *fsrc = P.feature + gb * Tsz * Fsz + 2 * Fsz + 27;
        #pragma unroll
        for (int q = 0; q < 10; ++q) xp[q] = fsrc[q];
        xp[10] = o0; xp[11] = o1; xp[12] = o2;
    }
}

extern "C" void kernel_launch(void *const *d_in, const int *in_sizes, int n_in,
                              void *d_out, int out_size) {
    Params P;
    P.feature = (const float *)d_in[0];
    P.w_m1 = (const float *)d_in[1];  P.b_m1 = (const float *)d_in[2];
    P.w_m2 = (const float *)d_in[3];  P.b_m2 = (const float *)d_in[4];
    P.w_t1 = (const float *)d_in[5];  P.b_t1 = (const float *)d_in[6];
    P.w_t2 = (const float *)d_in[7];  P.b_t2 = (const float *)d_in[8];
    P.w_s1 = (const float *)d_in[9];  P.b_s1 = (const float *)d_in[10];
    P.w_s2 = (const float *)d_in[11]; P.b_s2 = (const float *)d_in[12];
    P.w_lk = (const float *)d_in[13];
    P.w_lr = (const float *)d_in[14];
    P.b_l  = (const float *)d_in[15];
    P.w_p1 = (const float *)d_in[16]; P.b_p1 = (const float *)d_in[17];
    P.w_p2 = (const float *)d_in[18]; P.b_p2 = (const float *)d_in[19];
    P.w_p3 = (const float *)d_in[20]; P.b_p3 = (const float *)d_in[21];
    P.w_p4 = (const float *)d_in[22]; P.b_p4 = (const float *)d_in[23];
    P.w_p5 = (const float *)d_in[24]; P.b_p5 = (const float *)d_in[25];
    P.out = (float *)d_out;

    frontend_kernel<<<RGRID + Bsz / TBF, NTF>>>(P);
    lstm_fused_kernel<<<GRID_L, NT>>>(P);
}